// round 14
// baseline (speedup 1.0000x reference)
#include <cuda_runtime.h>
#include <math.h>

#define NB 64
#define NS 8192
#define NW 64
#define NM 16
#define NC 32
#define NL 4
#define NSPLIT 16
#define SCH (NS / NSPLIT)

// ---------------- device scratch (no cudaMalloc allowed) ----------------
__device__ float g_h[2][NB * NW * NS];        // ping-pong activations (b,i,s)
__device__ float g_tab[NC * NS];              // [kc][s]: rows 0..15 cos, 16..31 sin
__device__ float g_tab2[NS * NC];             // [s][kc] transposed copy
__device__ float g_ftp[NSPLIT][NB * NW * NC]; // split-K partial DFT sums
__device__ float g_ft[NB * NW * NC];          // reduced: fr rows 0..15, fi rows 16..31
__device__ float g_coef[NB * NC * NW];        // per b: [kc][o]
__device__ float g_xft[NB * 2 * NC];          // DFT of x channels
__device__ float g_cw0[2 * NW];               // conv_w[0] @ p_w^T  : [c][o]
__device__ float g_b0[NW];                    // conv_w[0] @ p_b    : [o]
__device__ float g_cwT[NL * NW * NW];         // conv_w transposed: [l][i][o]

// ---------------- packed f32x2 + cp.async helpers ----------------
static __device__ __forceinline__ void fma2(unsigned long long& d,
                                            unsigned long long a,
                                            unsigned long long b) {
    asm("fma.rn.f32x2 %0, %1, %2, %0;" : "+l"(d) : "l"(a), "l"(b));
}
static __device__ __forceinline__ unsigned long long pk2(float v) {
    unsigned long long r;
    asm("mov.b64 %0, {%1, %1};" : "=l"(r) : "f"(v));
    return r;
}
static __device__ __forceinline__ float2 up2(unsigned long long p) {
    float2 r;
    asm("mov.b64 {%0, %1}, %2;" : "=f"(r.x), "=f"(r.y) : "l"(p));
    return r;
}
#define CPA16(dst_u32, src_ptr) \
    asm volatile("cp.async.cg.shared.global [%0], [%1], 16;" :: "r"(dst_u32), "l"(src_ptr))
#define CPC() asm volatile("cp.async.commit_group;")
#define CPW(N) asm volatile("cp.async.wait_group %0;" :: "n"(N))
static __device__ __forceinline__ unsigned s2u(const void* p) {
    return (unsigned)__cvta_generic_to_shared(p);
}

// fast accurate tanh: 2 MUFU (EX2 + RCP), ~1e-6 abs error
static __device__ __forceinline__ float ftanh(float x) {
    float ax = fminf(fabsf(x), 10.0f);
    float e = __expf(2.0f * ax);
    float t = (e - 1.0f) * __fdividef(1.0f, e + 1.0f);
    return copysignf(t, x);
}

// ================= basis tables + layer-0 folded weights + conv transpose =================
__global__ void k_tab(const float* __restrict__ cw, const float* __restrict__ pw,
                      const float* __restrict__ pb) {
    int t = threadIdx.x;
    int blk = blockIdx.x;
    if (blk == 32) {                   // prep block: g_cw0, g_b0
        int o = t;
        if (o >= NW) return;
        float c0 = 0.f, c1 = 0.f, bv = 0.f;
#pragma unroll 8
        for (int i = 0; i < NW; i++) {
            float w = cw[o * NW + i];
            c0 = fmaf(w, pw[i], c0);
            c1 = fmaf(w, pw[NW + i], c1);
            bv = fmaf(w, pb[i], bv);
        }
        g_cw0[o] = c0;
        g_cw0[NW + o] = c1;
        g_b0[o] = bv;
        return;
    }
    if (blk >= 33) {                   // transpose conv_w for layer l = blk-33
        int l = blk - 33;
        for (int idx = t; idx < NW * NW; idx += 256) {
            int i = idx >> 6, o = idx & 63;
            g_cwT[((size_t)l * NW + i) * NW + o] = cw[((size_t)l * NW + o) * NW + i];
        }
        return;
    }
    int s = blk * 256 + t;
#pragma unroll
    for (int k = 0; k < NM; k++) {
        int ph = (k * s) & (NS - 1);
        float ang = (float)((double)ph * (6.283185307179586476925287 / (double)NS));
        float c, sn;
        sincosf(ang, &c, &sn);
        g_tab[k * NS + s] = c;
        g_tab[(k + NM) * NS + s] = sn;
        g_tab2[s * NC + k] = c;
        g_tab2[s * NC + NM + k] = sn;
    }
}

// ================= DFT of raw input x (2 channels) =================
__global__ void __launch_bounds__(256) k_xdft(const float* __restrict__ x) {
    int t = threadIdx.x;
    int w = t >> 5, lane = t & 31;
    int b = blockIdx.x;
    const float2* x2 = (const float2*)x + (size_t)b * NS;
    int k0 = w * 4;
    float acc[2][4];
#pragma unroll
    for (int c = 0; c < 2; c++)
#pragma unroll
        for (int k = 0; k < 4; k++) acc[c][k] = 0.f;
    for (int s = lane; s < NS; s += 32) {
        float2 xv = x2[s];
#pragma unroll
        for (int k = 0; k < 4; k++) {
            float tv = g_tab[(k0 + k) * NS + s];
            acc[0][k] = fmaf(xv.x, tv, acc[0][k]);
            acc[1][k] = fmaf(xv.y, tv, acc[1][k]);
        }
    }
#pragma unroll
    for (int off = 16; off > 0; off >>= 1)
#pragma unroll
        for (int c = 0; c < 2; c++)
#pragma unroll
            for (int k = 0; k < 4; k++)
                acc[c][k] += __shfl_xor_sync(0xffffffffu, acc[c][k], off);
    if (lane == 0) {
#pragma unroll
        for (int c = 0; c < 2; c++)
#pragma unroll
            for (int k = 0; k < 4; k++) {
                int kc = k0 + k;
                float v = acc[c][k] * (1.0f / NS);
                g_xft[(b * 2 + c) * NC + kc] = (kc < NM) ? v : -v;
            }
    }
}

// ================= forward DFT partials (layers >= 1) =================
// R11 double-buffered structure; tile repacked to 2 i x 8 kc per thread.
#define HS_STR 36
__global__ void __launch_bounds__(128) k_fwd(int cur) {
    __shared__ float Hs[2][64 * HS_STR];   // [i][s] padded rows
    __shared__ float Ts[2][32 * 32];       // [s][kc]
    int t = threadIdx.x;
    int kg = t & 3, ig = t >> 2;           // 4 kc-groups x 32 i-groups
    int i0 = ig * 2, kc0 = kg * 8;
    int b = blockIdx.y;
    int s0 = blockIdx.x * SCH;
    const float* hb = g_h[cur] + (size_t)(b * NW) * NS;

    unsigned long long acc[2][4];
#pragma unroll
    for (int j = 0; j < 2; j++)
#pragma unroll
        for (int k = 0; k < 4; k++) acc[j][k] = 0ull;

#define FWD_STAGE(c, bf) do {                                                   \
        int soff = s0 + (c) * 32;                                               \
        _Pragma("unroll")                                                       \
        for (int k2 = 0; k2 < 4; k2++) {                                        \
            int q = t + k2 * 128;                                               \
            int i = q >> 3, pc = q & 7;                                         \
            CPA16(s2u(&Hs[bf][i * HS_STR + pc * 4]),                            \
                  hb + (size_t)i * NS + soff + pc * 4);                         \
        }                                                                       \
        _Pragma("unroll")                                                       \
        for (int k2 = 0; k2 < 2; k2++) {                                        \
            int q = t + k2 * 128;                                               \
            int sr = q >> 3, pc = q & 7;                                        \
            CPA16(s2u(&Ts[bf][sr * 32 + pc * 4]),                               \
                  g_tab2 + (size_t)(soff + sr) * NC + pc * 4);                  \
        }                                                                       \
        CPC();                                                                  \
    } while (0)

    FWD_STAGE(0, 0);
    const int NCH = SCH / 32;   // 16
    for (int c = 0; c < NCH; c++) {
        if (c + 1 < NCH) { FWD_STAGE(c + 1, (c + 1) & 1); CPW(1); }
        else CPW(0);
        __syncthreads();
        const float* Hc = Hs[c & 1];
        const float* Tc = Ts[c & 1];
#pragma unroll 4
        for (int s = 0; s < 32; s += 4) {
            float4 hv0 = *(const float4*)&Hc[i0 * HS_STR + s];
            float4 hv1 = *(const float4*)&Hc[(i0 + 1) * HS_STR + s];
#pragma unroll
            for (int ss = 0; ss < 4; ss++) {
                ulonglong2 tb0 = *(const ulonglong2*)&Tc[(s + ss) * 32 + kc0];
                ulonglong2 tb1 = *(const ulonglong2*)&Tc[(s + ss) * 32 + kc0 + 4];
                float h0s = (ss == 0) ? hv0.x : (ss == 1) ? hv0.y
                          : (ss == 2) ? hv0.z : hv0.w;
                float h1s = (ss == 0) ? hv1.x : (ss == 1) ? hv1.y
                          : (ss == 2) ? hv1.z : hv1.w;
                unsigned long long h0 = pk2(h0s), h1 = pk2(h1s);
                fma2(acc[0][0], h0, tb0.x); fma2(acc[0][1], h0, tb0.y);
                fma2(acc[0][2], h0, tb1.x); fma2(acc[0][3], h0, tb1.y);
                fma2(acc[1][0], h1, tb0.x); fma2(acc[1][1], h1, tb0.y);
                fma2(acc[1][2], h1, tb1.x); fma2(acc[1][3], h1, tb1.y);
            }
        }
        __syncthreads();
    }
    float* fp = g_ftp[blockIdx.x] + (b * NW) * NC;
#pragma unroll
    for (int j = 0; j < 2; j++) {
        float2 c0 = up2(acc[j][0]), c1 = up2(acc[j][1]);
        float2 c2 = up2(acc[j][2]), c3 = up2(acc[j][3]);
        *(float4*)&fp[(i0 + j) * NC + kc0] = make_float4(c0.x, c0.y, c1.x, c1.y);
        *(float4*)&fp[(i0 + j) * NC + kc0 + 4] = make_float4(c2.x, c2.y, c3.x, c3.y);
    }
#undef FWD_STAGE
}

// ================= split-K reduce =================
__global__ void __launch_bounds__(256) k_red() {
    int idx = blockIdx.x * 256 + threadIdx.x;
    float v = 0.f;
#pragma unroll
    for (int sp = 0; sp < NSPLIT; sp++) v += g_ftp[sp][idx];
    int kc = idx & 31;
    g_ft[idx] = (kc < NM ? v : -v) * (1.0f / NS);
}

// ================= mode mix (l==0 reads x-spectrum directly) =================
__global__ void __launch_bounds__(256) k_mix2(const float* __restrict__ wr,
                                              const float* __restrict__ wi,
                                              const float* __restrict__ cb, int l,
                                              const float* __restrict__ pw,
                                              const float* __restrict__ pb) {
    __shared__ float wrs[64 * 65], wis[64 * 65];
    __shared__ float frs[16 * 64], fis[16 * 64];
    int t = threadIdx.x;
    int k = blockIdx.x, bg = blockIdx.y;
    const float* wrl = wr + (size_t)l * NW * NW * NM;
    const float* wil = wi + (size_t)l * NW * NW * NM;
    for (int idx = t; idx < 4096; idx += 256) {
        int i = idx >> 6, o = idx & 63;
        wrs[i * 65 + o] = wrl[(i * 64 + o) * NM + k];
        wis[i * 65 + o] = wil[(i * 64 + o) * NM + k];
    }
    for (int idx = t; idx < 1024; idx += 256) {
        int b16 = idx >> 6, i = idx & 63;
        int b = bg * 16 + b16;
        if (l == 0) {
            float x0c = g_xft[(b * 2) * NC + k],      x1c = g_xft[(b * 2 + 1) * NC + k];
            float x0s = g_xft[(b * 2) * NC + NM + k], x1s = g_xft[(b * 2 + 1) * NC + NM + k];
            float fr = pw[i] * x0c + pw[NW + i] * x1c;
            if (k == 0) fr += pb[i];
            frs[b16 * 64 + i] = fr;
            fis[b16 * 64 + i] = pw[i] * x0s + pw[NW + i] * x1s;
        } else {
            frs[b16 * 64 + i] = g_ft[(b * NW + i) * NC + k];
            fis[b16 * 64 + i] = g_ft[(b * NW + i) * NC + NM + k];
        }
    }
    __syncthreads();
#pragma unroll
    for (int u = 0; u < 4; u++) {
        int oi = t + u * 256;
        int o = oi & 63, b16 = oi >> 6;
        float sr = 0.f, si = 0.f;
#pragma unroll 8
        for (int i = 0; i < 64; i++) {
            float fr = frs[b16 * 64 + i], fi = fis[b16 * 64 + i];
            float a = wrs[i * 65 + o], c = wis[i * 65 + o];
            sr = fmaf(fr, a, sr); sr = fmaf(-fi, c, sr);
            si = fmaf(fr, c, si); si = fmaf(fi, a, si);
        }
        int b = bg * 16 + b16;
        float* cf = g_coef + (size_t)b * NC * NW;      // [kc][o] layout
        if (k == 0) {
            float base = sr + cb[l * NW + o];
            if (l == 0) base += g_b0[o];
            cf[o] = base; cf[NM * NW + o] = 0.f;
        } else {
            cf[k * NW + o] = 2.f * sr;
            cf[(NM + k) * NW + o] = -2.f * si;
        }
    }
}

// o-packed GEMM step: A pairs load directly as ulonglong2 (no MOV);
// B = 4 broadcast s-scalars (4 pk2). acc[s 0..3][o-pair 0..7].
#define GEMM_STEP_O(jj, Bc, it) do {                                            \
        float4 bv = *(const float4*)&(Bc)[(it) * 256 + sg * 4];                 \
        unsigned long long b0 = pk2(bv.x), b1 = pk2(bv.y),                      \
                           b2 = pk2(bv.z), b3 = pk2(bv.w);                      \
        const float* ap = &Ad[(jj) * 64 + o0];                                  \
        ulonglong2 A0 = *(const ulonglong2*)(ap);                               \
        ulonglong2 A1 = *(const ulonglong2*)(ap + 4);                           \
        ulonglong2 A2 = *(const ulonglong2*)(ap + 8);                           \
        ulonglong2 A3 = *(const ulonglong2*)(ap + 12);                          \
        fma2(acc[0][0], A0.x, b0); fma2(acc[0][1], A0.y, b0);                   \
        fma2(acc[0][2], A1.x, b0); fma2(acc[0][3], A1.y, b0);                   \
        fma2(acc[0][4], A2.x, b0); fma2(acc[0][5], A2.y, b0);                   \
        fma2(acc[0][6], A3.x, b0); fma2(acc[0][7], A3.y, b0);                   \
        fma2(acc[1][0], A0.x, b1); fma2(acc[1][1], A0.y, b1);                   \
        fma2(acc[1][2], A1.x, b1); fma2(acc[1][3], A1.y, b1);                   \
        fma2(acc[1][4], A2.x, b1); fma2(acc[1][5], A2.y, b1);                   \
        fma2(acc[1][6], A3.x, b1); fma2(acc[1][7], A3.y, b1);                   \
        fma2(acc[2][0], A0.x, b2); fma2(acc[2][1], A0.y, b2);                   \
        fma2(acc[2][2], A1.x, b2); fma2(acc[2][3], A1.y, b2);                   \
        fma2(acc[2][4], A2.x, b2); fma2(acc[2][5], A2.y, b2);                   \
        fma2(acc[2][6], A3.x, b2); fma2(acc[2][7], A3.y, b2);                   \
        fma2(acc[3][0], A0.x, b3); fma2(acc[3][1], A0.y, b3);                   \
        fma2(acc[3][2], A1.x, b3); fma2(acc[3][3], A1.y, b3);                   \
        fma2(acc[3][4], A2.x, b3); fma2(acc[3][5], A2.y, b3);                   \
        fma2(acc[3][6], A3.x, b3); fma2(acc[3][7], A3.y, b3);                   \
    } while (0)

// shared epilogue: unpack o-pairs, tanh, STG.128 per o row
#define INV_EPILOGUE(dstbase) do {                                              \
        float* dst = (dstbase) + sg * 4;                                        \
        _Pragma("unroll")                                                       \
        for (int p = 0; p < 8; p++) {                                           \
            int o = o0 + p * 2;                                                 \
            float2 v0 = up2(acc[0][p]), v1 = up2(acc[1][p]);                    \
            float2 v2 = up2(acc[2][p]), v3 = up2(acc[3][p]);                    \
            *(float4*)&dst[(size_t)o * NS] =                                    \
                make_float4(ftanh(v0.x), ftanh(v1.x), ftanh(v2.x), ftanh(v3.x));\
            *(float4*)&dst[(size_t)(o + 1) * NS] =                              \
                make_float4(ftanh(v0.y), ftanh(v1.y), ftanh(v2.y), ftanh(v3.y));\
        }                                                                       \
    } while (0)

// ================= fused irfft + conv + tanh (layers >= 1) =================
__global__ void __launch_bounds__(256, 2) k_inv(int l, int cur, int nxt) {
    __shared__ float Ad[96 * 64];
    __shared__ float Bs[2][8 * 256];
    int t = threadIdx.x;
    int og = t >> 6, sg = t & 63;
    int o0 = og * 16;
    int b = blockIdx.y;
    int s0 = blockIdx.x * 256;
    const float* hb = g_h[cur] + (size_t)(b * NW) * NS;
    const float* cfb = g_coef + (size_t)b * NC * NW;

    // async A-prologue: 96 rows x 64 o, all contiguous 16B copies
#pragma unroll
    for (int k2 = 0; k2 < 6; k2++) {
        int q = t + k2 * 256;
        int r = q >> 4, pc = q & 15;
        const float* src = (r < 32)
            ? (cfb + r * NW + pc * 4)
            : (g_cwT + ((size_t)l * NW + (r - 32)) * NW + pc * 4);
        CPA16(s2u(&Ad[r * 64 + pc * 4]), src);
    }

#define INV_STAGE(ch, bf) do {                                                  \
        _Pragma("unroll")                                                       \
        for (int k2 = 0; k2 < 2; k2++) {                                        \
            int q = t + k2 * 256;                                               \
            int it = q >> 6, pc = q & 63;                                       \
            int j = (ch) * 8 + it;                                              \
            const float* src = (j < 32)                                         \
                ? (g_tab + (size_t)j * NS + s0 + pc * 4)                        \
                : (hb + (size_t)(j - 32) * NS + s0 + pc * 4);                   \
            CPA16(s2u(&Bs[bf][it * 256 + pc * 4]), src);                        \
        }                                                                       \
        CPC();                                                                  \
    } while (0)

    unsigned long long acc[4][8];
#pragma unroll
    for (int ss = 0; ss < 4; ss++)
#pragma unroll
        for (int p = 0; p < 8; p++) acc[ss][p] = 0ull;

    INV_STAGE(0, 0);   // commits A + chunk0 as group 0
    for (int ch = 0; ch < 12; ch++) {
        if (ch < 11) { INV_STAGE(ch + 1, (ch + 1) & 1); CPW(1); }
        else CPW(0);
        __syncthreads();
        const float* Bc = Bs[ch & 1];
#pragma unroll
        for (int it = 0; it < 8; it++)
            GEMM_STEP_O(ch * 8 + it, Bc, it);
        __syncthreads();
    }
#undef INV_STAGE
    INV_EPILOGUE(g_h[nxt] + (size_t)(b * NW) * NS + s0);
}

// ================= layer-0 fused inverse: K = 32 basis + 2 x channels =================
__global__ void __launch_bounds__(256, 2) k_inv0(const float* __restrict__ x, int nxt) {
    __shared__ float Ad[34 * 64];
    __shared__ float Bs[2][16 * 256];
    int t = threadIdx.x;
    int og = t >> 6, sg = t & 63;
    int o0 = og * 16;
    int b = blockIdx.y;
    int s0 = blockIdx.x * 256;
    const float* cfb = g_coef + (size_t)b * NC * NW;

    // async A-prologue: 34 rows, contiguous copies (coef + g_cw0)
#pragma unroll
    for (int k2 = 0; k2 < 3; k2++) {
        int q = t + k2 * 256;
        if (q < 544) {
            int r = q >> 4, pc = q & 15;
            const float* src = (r < 32) ? (cfb + r * NW + pc * 4)
                                        : (g_cw0 + (r - 32) * NW + pc * 4);
            CPA16(s2u(&Ad[r * 64 + pc * 4]), src);
        }
    }

    unsigned long long acc[4][8];
#pragma unroll
    for (int ss = 0; ss < 4; ss++)
#pragma unroll
        for (int p = 0; p < 8; p++) acc[ss][p] = 0ull;

    // prefetch both tab chunks (chunk0 commits together with A as group 0)
#pragma unroll
    for (int ch = 0; ch < 2; ch++) {
#pragma unroll
        for (int k2 = 0; k2 < 4; k2++) {
            int q = t + k2 * 256;
            int it = q >> 6, pc = q & 63;
            int j = ch * 16 + it;
            CPA16(s2u(&Bs[ch][it * 256 + pc * 4]),
                  g_tab + (size_t)j * NS + s0 + pc * 4);
        }
        CPC();
    }
    for (int ch = 0; ch < 2; ch++) {
        if (ch == 0) CPW(1); else CPW(0);
        __syncthreads();
        const float* Bc = Bs[ch];
#pragma unroll 4
        for (int it = 0; it < 16; it++)
            GEMM_STEP_O(ch * 16 + it, Bc, it);
        __syncthreads();
    }
    // x-channel rows (interleaved source -> manual stage)
    {
        const float2* x2 = (const float2*)x + (size_t)b * NS + s0;
        float2 xv = x2[t];
        Bs[0][0 * 256 + t] = xv.x;
        Bs[0][1 * 256 + t] = xv.y;
    }
    __syncthreads();
#pragma unroll
    for (int it = 0; it < 2; it++)
        GEMM_STEP_O(32 + it, Bs[0], it);
    INV_EPILOGUE(g_h[nxt] + (size_t)(b * NW) * NS + s0);
}

// ================= head =================
__global__ void __launch_bounds__(256, 2) k_head(const float* __restrict__ qw,
                                                 const float* __restrict__ qb,
                                                 const float* __restrict__ ow,
                                                 const float* __restrict__ ob,
                                                 float* __restrict__ out, int cur) {
    __shared__ float Aq[64 * 36];
    __shared__ float Bq[2][16 * 260];
    int t = threadIdx.x;
    int qg = t >> 5, sg = t & 31;
    int b = blockIdx.y;
    int s0 = blockIdx.x * 256;
    for (int idx = t; idx < 64 * 32; idx += 256) {
        int i = idx >> 5, q = idx & 31;
        Aq[i * 36 + q] = qw[i * 32 + q];
    }
    unsigned long long acc[4][4];
#pragma unroll
    for (int qq = 0; qq < 4; qq++)
#pragma unroll
        for (int sp = 0; sp < 4; sp++) acc[qq][sp] = 0ull;

    const float* hb = g_h[cur] + (size_t)(b * NW) * NS;
#define HEAD_STAGE(ch, bf) do {                                                 \
        _Pragma("unroll")                                                       \
        for (int k2 = 0; k2 < 4; k2++) {                                        \
            int q = t + k2 * 256;                                               \
            int it = q >> 6, pc = q & 63;                                       \
            CPA16(s2u(&Bq[bf][it * 260 + pc * 4]),                              \
                  hb + (size_t)((ch) * 16 + it) * NS + s0 + pc * 4);            \
        }                                                                       \
        CPC();                                                                  \
    } while (0)

    HEAD_STAGE(0, 0);
    for (int ch = 0; ch < 4; ch++) {
        if (ch < 3) { HEAD_STAGE(ch + 1, (ch + 1) & 1); CPW(1); }
        else CPW(0);
        __syncthreads();
        const float* Bc = Bq[ch & 1];
#pragma unroll 4
        for (int it = 0; it < 16; it++) {
            int i = ch * 16 + it;
            float4 a0 = *(const float4*)&Aq[i * 36 + qg * 4];
            ulonglong2 B0 = *(const ulonglong2*)&Bc[it * 260 + sg * 4];
            ulonglong2 B1 = *(const ulonglong2*)&Bc[it * 260 + 128 + sg * 4];
            unsigned long long ad;
            ad = pk2(a0.x);
            fma2(acc[0][0], ad, B0.x); fma2(acc[0][1], ad, B0.y);
            fma2(acc[0][2], ad, B1.x); fma2(acc[0][3], ad, B1.y);
            ad = pk2(a0.y);
            fma2(acc[1][0], ad, B0.x); fma2(acc[1][1], ad, B0.y);
            fma2(acc[1][2], ad, B1.x); fma2(acc[1][3], ad, B1.y);
            ad = pk2(a0.z);
            fma2(acc[2][0], ad, B0.x); fma2(acc[2][1], ad, B0.y);
            fma2(acc[2][2], ad, B1.x); fma2(acc[2][3], ad, B1.y);
            ad = pk2(a0.w);
            fma2(acc[3][0], ad, B0.x); fma2(acc[3][1], ad, B0.y);
            fma2(acc[3][2], ad, B1.x); fma2(acc[3][3], ad, B1.y);
        }
        __syncthreads();
    }
#undef HEAD_STAGE
    float* BQ = &Bq[0][0];   // reuse both halves as qa[32][260]
#pragma unroll
    for (int qq = 0; qq < 4; qq++) {
        int q = qg * 4 + qq;
        float qbv = qb[q];
#pragma unroll
        for (int sp = 0; sp < 4; sp++) {
            float2 v = up2(acc[qq][sp]);
            int sl = (sp >> 1) * 128 + sg * 4 + (sp & 1) * 2;
            BQ[q * 260 + sl] = ftanh(v.x + qbv);
            BQ[q * 260 + sl + 1] = ftanh(v.y + qbv);
        }
    }
    __syncthreads();
    float r = ob[0];
#pragma unroll 8
    for (int q = 0; q < 32; q++) r = fmaf(BQ[q * 260 + t], ow[q], r);
    out[(size_t)b * NS + s0 + t] = r;
}

// ================= launcher =================
extern "C" void kernel_launch(void* const* d_in, const int* in_sizes, int n_in,
                              void* d_out, int out_size) {
    const float* x  = (const float*)d_in[0];
    const float* pw = (const float*)d_in[1];
    const float* pb = (const float*)d_in[2];
    const float* wr = (const float*)d_in[3];
    const float* wi = (const float*)d_in[4];
    const float* cw = (const float*)d_in[5];
    const float* cb = (const float*)d_in[6];
    const float* qw = (const float*)d_in[7];
    const float* qb = (const float*)d_in[8];
    const float* ow = (const float*)d_in[9];
    const float* ob = (const float*)d_in[10];
    float* out = (float*)d_out;

    k_tab<<<37, 256>>>(cw, pw, pb);                       // 1
    k_xdft<<<NB, 256>>>(x);                               // 2
    k_mix2<<<dim3(NM, 4), 256>>>(wr, wi, cb, 0, pw, pb);  // 3
    k_inv0<<<dim3(NS / 256, NB), 256>>>(x, 0);            // 4  <- profiled slot
    int cur = 0;
    for (int l = 1; l < NL; l++) {
        k_fwd<<<dim3(NSPLIT, NB), 128>>>(cur);
        k_red<<<(NB * NW * NC) / 256, 256>>>();
        k_mix2<<<dim3(NM, 4), 256>>>(wr, wi, cb, l, pw, pb);
        k_inv<<<dim3(NS / 256, NB), 256>>>(l, cur, 1 - cur);
        cur ^= 1;
    }
    k_head<<<dim3(NS / 256, NB), 256>>>(qw, qb, ow, ob, out, cur);
}

// round 15
// speedup vs baseline: 1.0489x; 1.0489x over previous
#include <cuda_runtime.h>
#include <math.h>

#define NB 64
#define NS 8192
#define NW 64
#define NM 16
#define NC 32
#define NL 4
#define NSPLIT 16
#define SCH (NS / NSPLIT)

// ---------------- device scratch (no cudaMalloc allowed) ----------------
__device__ float g_h[2][NB * NW * NS];        // ping-pong activations (b,i,s)
__device__ float g_tab[NC * NS];              // [kc][s]: rows 0..15 cos, 16..31 sin
__device__ float g_tab2[NS * NC];             // [s][kc] transposed copy
__device__ float g_ftp[NSPLIT][NB * NW * NC]; // split-K partial DFT sums
__device__ float g_ft[NB * NW * NC];          // reduced: fr rows 0..15, fi rows 16..31
__device__ float g_coef[NB * NC * NW];        // per b: [kc][o]
__device__ float g_xft[NB * 2 * NC];          // DFT of x channels
__device__ float g_cw0[2 * NW];               // conv_w[0] @ p_w^T  : [c][o]
__device__ float g_b0[NW];                    // conv_w[0] @ p_b    : [o]
__device__ float g_cwT[NL * NW * NW];         // conv_w transposed: [l][i][o]

// ---------------- packed f32x2 + cp.async helpers ----------------
static __device__ __forceinline__ void fma2(unsigned long long& d,
                                            unsigned long long a,
                                            unsigned long long b) {
    asm("fma.rn.f32x2 %0, %1, %2, %0;" : "+l"(d) : "l"(a), "l"(b));
}
static __device__ __forceinline__ unsigned long long pk2(float v) {
    unsigned long long r;
    asm("mov.b64 %0, {%1, %1};" : "=l"(r) : "f"(v));
    return r;
}
static __device__ __forceinline__ float2 up2(unsigned long long p) {
    float2 r;
    asm("mov.b64 {%0, %1}, %2;" : "=f"(r.x), "=f"(r.y) : "l"(p));
    return r;
}
#define CPA16(dst_u32, src_ptr) \
    asm volatile("cp.async.cg.shared.global [%0], [%1], 16;" :: "r"(dst_u32), "l"(src_ptr))
#define CPC() asm volatile("cp.async.commit_group;")
#define CPW(N) asm volatile("cp.async.wait_group %0;" :: "n"(N))
static __device__ __forceinline__ unsigned s2u(const void* p) {
    return (unsigned)__cvta_generic_to_shared(p);
}

// fast accurate tanh: 2 MUFU (EX2 + RCP), ~1e-6 abs error
static __device__ __forceinline__ float ftanh(float x) {
    float ax = fminf(fabsf(x), 10.0f);
    float e = __expf(2.0f * ax);
    float t = (e - 1.0f) * __fdividef(1.0f, e + 1.0f);
    return copysignf(t, x);
}

// ================= basis tables + layer-0 folded weights + conv transpose =================
__global__ void k_tab(const float* __restrict__ cw, const float* __restrict__ pw,
                      const float* __restrict__ pb) {
    int t = threadIdx.x;
    int blk = blockIdx.x;
    if (blk == 32) {                   // prep block: g_cw0, g_b0
        int o = t;
        if (o >= NW) return;
        float c0 = 0.f, c1 = 0.f, bv = 0.f;
#pragma unroll 8
        for (int i = 0; i < NW; i++) {
            float w = cw[o * NW + i];
            c0 = fmaf(w, pw[i], c0);
            c1 = fmaf(w, pw[NW + i], c1);
            bv = fmaf(w, pb[i], bv);
        }
        g_cw0[o] = c0;
        g_cw0[NW + o] = c1;
        g_b0[o] = bv;
        return;
    }
    if (blk >= 33) {                   // transpose conv_w for layer l = blk-33
        int l = blk - 33;
        for (int idx = t; idx < NW * NW; idx += 256) {
            int i = idx >> 6, o = idx & 63;
            g_cwT[((size_t)l * NW + i) * NW + o] = cw[((size_t)l * NW + o) * NW + i];
        }
        return;
    }
    int s = blk * 256 + t;
#pragma unroll
    for (int k = 0; k < NM; k++) {
        int ph = (k * s) & (NS - 1);
        float ang = (float)((double)ph * (6.283185307179586476925287 / (double)NS));
        float c, sn;
        sincosf(ang, &c, &sn);
        g_tab[k * NS + s] = c;
        g_tab[(k + NM) * NS + s] = sn;
        g_tab2[s * NC + k] = c;
        g_tab2[s * NC + NM + k] = sn;
    }
}

// ================= DFT of raw input x (2 channels) =================
__global__ void __launch_bounds__(256) k_xdft(const float* __restrict__ x) {
    int t = threadIdx.x;
    int w = t >> 5, lane = t & 31;
    int b = blockIdx.x;
    const float2* x2 = (const float2*)x + (size_t)b * NS;
    int k0 = w * 4;
    float acc[2][4];
#pragma unroll
    for (int c = 0; c < 2; c++)
#pragma unroll
        for (int k = 0; k < 4; k++) acc[c][k] = 0.f;
    for (int s = lane; s < NS; s += 32) {
        float2 xv = x2[s];
#pragma unroll
        for (int k = 0; k < 4; k++) {
            float tv = g_tab[(k0 + k) * NS + s];
            acc[0][k] = fmaf(xv.x, tv, acc[0][k]);
            acc[1][k] = fmaf(xv.y, tv, acc[1][k]);
        }
    }
#pragma unroll
    for (int off = 16; off > 0; off >>= 1)
#pragma unroll
        for (int c = 0; c < 2; c++)
#pragma unroll
            for (int k = 0; k < 4; k++)
                acc[c][k] += __shfl_xor_sync(0xffffffffu, acc[c][k], off);
    if (lane == 0) {
#pragma unroll
        for (int c = 0; c < 2; c++)
#pragma unroll
            for (int k = 0; k < 4; k++) {
                int kc = k0 + k;
                float v = acc[c][k] * (1.0f / NS);
                g_xft[(b * 2 + c) * NC + kc] = (kc < NM) ? v : -v;
            }
    }
}

// ================= forward DFT partials (layers >= 1) — exact R11 form =================
__global__ void __launch_bounds__(128) k_fwd(int cur) {
    __shared__ float Hs[2][64 * 32];   // [i][s]
    __shared__ float Ts[2][32 * 32];   // [s][kc]
    int t = threadIdx.x;
    int kg = t & 7, ig = t >> 3;
    int i0 = ig * 4, kc0 = kg * 4;
    int b = blockIdx.y;
    int s0 = blockIdx.x * SCH;
    const float* hb = g_h[cur] + (size_t)(b * NW) * NS;

    unsigned long long acc[4][2];
#pragma unroll
    for (int j = 0; j < 4; j++) { acc[j][0] = 0ull; acc[j][1] = 0ull; }

#define FWD_STAGE(c, bf) do {                                                   \
        int soff = s0 + (c) * 32;                                               \
        _Pragma("unroll")                                                       \
        for (int k2 = 0; k2 < 4; k2++) {                                        \
            int q = t + k2 * 128;                                               \
            int i = q >> 3, pc = q & 7;                                         \
            CPA16(s2u(&Hs[bf][i * 32 + pc * 4]),                                \
                  hb + (size_t)i * NS + soff + pc * 4);                         \
        }                                                                       \
        _Pragma("unroll")                                                       \
        for (int k2 = 0; k2 < 2; k2++) {                                        \
            int q = t + k2 * 128;                                               \
            int sr = q >> 3, pc = q & 7;                                        \
            CPA16(s2u(&Ts[bf][sr * 32 + pc * 4]),                               \
                  g_tab2 + (size_t)(soff + sr) * NC + pc * 4);                  \
        }                                                                       \
        CPC();                                                                  \
    } while (0)

    FWD_STAGE(0, 0);
    const int NCH = SCH / 32;   // 16
    for (int c = 0; c < NCH; c++) {
        if (c + 1 < NCH) { FWD_STAGE(c + 1, (c + 1) & 1); CPW(1); }
        else CPW(0);
        __syncthreads();
        const float* Hc = Hs[c & 1];
        const float* Tc = Ts[c & 1];
#pragma unroll 4
        for (int s = 0; s < 32; s += 4) {
            float4 hv[4];
#pragma unroll
            for (int j = 0; j < 4; j++)
                hv[j] = *(const float4*)&Hc[(i0 + j) * 32 + s];
#pragma unroll
            for (int ss = 0; ss < 4; ss++) {
                ulonglong2 tb = *(const ulonglong2*)&Tc[(s + ss) * 32 + kc0];
#pragma unroll
                for (int j = 0; j < 4; j++) {
                    float h = (ss == 0) ? hv[j].x : (ss == 1) ? hv[j].y
                             : (ss == 2) ? hv[j].z : hv[j].w;
                    unsigned long long a = pk2(h);
                    fma2(acc[j][0], a, tb.x);
                    fma2(acc[j][1], a, tb.y);
                }
            }
        }
        __syncthreads();
    }
    float* fp = g_ftp[blockIdx.x] + (b * NW) * NC;
#pragma unroll
    for (int j = 0; j < 4; j++) {
        float2 c0 = up2(acc[j][0]), c1 = up2(acc[j][1]);
        *(float4*)&fp[(i0 + j) * NC + kc0] = make_float4(c0.x, c0.y, c1.x, c1.y);
    }
#undef FWD_STAGE
}

// ================= split-K reduce =================
__global__ void __launch_bounds__(256) k_red() {
    int idx = blockIdx.x * 256 + threadIdx.x;
    float v = 0.f;
#pragma unroll
    for (int sp = 0; sp < NSPLIT; sp++) v += g_ftp[sp][idx];
    int kc = idx & 31;
    g_ft[idx] = (kc < NM ? v : -v) * (1.0f / NS);
}

// ================= mode mix: grid (NM, 16), 4 batches/block =================
__global__ void __launch_bounds__(256) k_mix2(const float* __restrict__ wr,
                                              const float* __restrict__ wi,
                                              const float* __restrict__ cb, int l,
                                              const float* __restrict__ pw,
                                              const float* __restrict__ pb) {
    __shared__ float wrs[64 * 65], wis[64 * 65];
    __shared__ float frs[4 * 64], fis[4 * 64];
    int t = threadIdx.x;
    int k = blockIdx.x, bg = blockIdx.y;
    const float* wrl = wr + (size_t)l * NW * NW * NM;
    const float* wil = wi + (size_t)l * NW * NW * NM;
    for (int idx = t; idx < 4096; idx += 256) {
        int i = idx >> 6, o = idx & 63;
        wrs[i * 65 + o] = wrl[(i * 64 + o) * NM + k];
        wis[i * 65 + o] = wil[(i * 64 + o) * NM + k];
    }
    {
        int b4 = t >> 6, i = t & 63;
        int b = bg * 4 + b4;
        if (l == 0) {
            float x0c = g_xft[(b * 2) * NC + k],      x1c = g_xft[(b * 2 + 1) * NC + k];
            float x0s = g_xft[(b * 2) * NC + NM + k], x1s = g_xft[(b * 2 + 1) * NC + NM + k];
            float fr = pw[i] * x0c + pw[NW + i] * x1c;
            if (k == 0) fr += pb[i];
            frs[b4 * 64 + i] = fr;
            fis[b4 * 64 + i] = pw[i] * x0s + pw[NW + i] * x1s;
        } else {
            frs[b4 * 64 + i] = g_ft[(b * NW + i) * NC + k];
            fis[b4 * 64 + i] = g_ft[(b * NW + i) * NC + NM + k];
        }
    }
    __syncthreads();
    {
        int o = t & 63, b4 = t >> 6;
        float sr = 0.f, si = 0.f;
#pragma unroll 8
        for (int i = 0; i < 64; i++) {
            float fr = frs[b4 * 64 + i], fi = fis[b4 * 64 + i];
            float a = wrs[i * 65 + o], c = wis[i * 65 + o];
            sr = fmaf(fr, a, sr); sr = fmaf(-fi, c, sr);
            si = fmaf(fr, c, si); si = fmaf(fi, a, si);
        }
        int b = bg * 4 + b4;
        float* cf = g_coef + (size_t)b * NC * NW;      // [kc][o] layout
        if (k == 0) {
            float base = sr + cb[l * NW + o];
            if (l == 0) base += g_b0[o];
            cf[o] = base; cf[NM * NW + o] = 0.f;
        } else {
            cf[k * NW + o] = 2.f * sr;
            cf[(NM + k) * NW + o] = -2.f * si;
        }
    }
}

// o-packed GEMM step: A pairs load directly as ulonglong2 (no MOV);
// B = 4 broadcast s-scalars (4 pk2). acc[s 0..3][o-pair 0..7].
#define GEMM_STEP_O(jj, Bc, it) do {                                            \
        float4 bv = *(const float4*)&(Bc)[(it) * 256 + sg * 4];                 \
        unsigned long long b0 = pk2(bv.x), b1 = pk2(bv.y),                      \
                           b2 = pk2(bv.z), b3 = pk2(bv.w);                      \
        const float* ap = &Ad[(jj) * 64 + o0];                                  \
        ulonglong2 A0 = *(const ulonglong2*)(ap);                               \
        ulonglong2 A1 = *(const ulonglong2*)(ap + 4);                           \
        ulonglong2 A2 = *(const ulonglong2*)(ap + 8);                           \
        ulonglong2 A3 = *(const ulonglong2*)(ap + 12);                          \
        fma2(acc[0][0], A0.x, b0); fma2(acc[0][1], A0.y, b0);                   \
        fma2(acc[0][2], A1.x, b0); fma2(acc[0][3], A1.y, b0);                   \
        fma2(acc[0][4], A2.x, b0); fma2(acc[0][5], A2.y, b0);                   \
        fma2(acc[0][6], A3.x, b0); fma2(acc[0][7], A3.y, b0);                   \
        fma2(acc[1][0], A0.x, b1); fma2(acc[1][1], A0.y, b1);                   \
        fma2(acc[1][2], A1.x, b1); fma2(acc[1][3], A1.y, b1);                   \
        fma2(acc[1][4], A2.x, b1); fma2(acc[1][5], A2.y, b1);                   \
        fma2(acc[1][6], A3.x, b1); fma2(acc[1][7], A3.y, b1);                   \
        fma2(acc[2][0], A0.x, b2); fma2(acc[2][1], A0.y, b2);                   \
        fma2(acc[2][2], A1.x, b2); fma2(acc[2][3], A1.y, b2);                   \
        fma2(acc[2][4], A2.x, b2); fma2(acc[2][5], A2.y, b2);                   \
        fma2(acc[2][6], A3.x, b2); fma2(acc[2][7], A3.y, b2);                   \
        fma2(acc[3][0], A0.x, b3); fma2(acc[3][1], A0.y, b3);                   \
        fma2(acc[3][2], A1.x, b3); fma2(acc[3][3], A1.y, b3);                   \
        fma2(acc[3][4], A2.x, b3); fma2(acc[3][5], A2.y, b3);                   \
        fma2(acc[3][6], A3.x, b3); fma2(acc[3][7], A3.y, b3);                   \
    } while (0)

// shared epilogue: unpack o-pairs, tanh, STG.128 per o row
#define INV_EPILOGUE(dstbase) do {                                              \
        float* dst = (dstbase) + sg * 4;                                        \
        _Pragma("unroll")                                                       \
        for (int p = 0; p < 8; p++) {                                           \
            int o = o0 + p * 2;                                                 \
            float2 v0 = up2(acc[0][p]), v1 = up2(acc[1][p]);                    \
            float2 v2 = up2(acc[2][p]), v3 = up2(acc[3][p]);                    \
            *(float4*)&dst[(size_t)o * NS] =                                    \
                make_float4(ftanh(v0.x), ftanh(v1.x), ftanh(v2.x), ftanh(v3.x));\
            *(float4*)&dst[(size_t)(o + 1) * NS] =                              \
                make_float4(ftanh(v0.y), ftanh(v1.y), ftanh(v2.y), ftanh(v3.y));\
        }                                                                       \
    } while (0)

// ================= fused irfft + conv + tanh (layers >= 1) =================
__global__ void __launch_bounds__(256, 2) k_inv(int l, int cur, int nxt) {
    __shared__ float Ad[96 * 64];
    __shared__ float Bs[2][8 * 256];
    int t = threadIdx.x;
    int og = t >> 6, sg = t & 63;
    int o0 = og * 16;
    int b = blockIdx.y;
    int s0 = blockIdx.x * 256;
    const float* hb = g_h[cur] + (size_t)(b * NW) * NS;
    const float* cfb = g_coef + (size_t)b * NC * NW;

    // async A-prologue: 96 rows x 64 o, all contiguous 16B copies
#pragma unroll
    for (int k2 = 0; k2 < 6; k2++) {
        int q = t + k2 * 256;
        int r = q >> 4, pc = q & 15;
        const float* src = (r < 32)
            ? (cfb + r * NW + pc * 4)
            : (g_cwT + ((size_t)l * NW + (r - 32)) * NW + pc * 4);
        CPA16(s2u(&Ad[r * 64 + pc * 4]), src);
    }

#define INV_STAGE(ch, bf) do {                                                  \
        _Pragma("unroll")                                                       \
        for (int k2 = 0; k2 < 2; k2++) {                                        \
            int q = t + k2 * 256;                                               \
            int it = q >> 6, pc = q & 63;                                       \
            int j = (ch) * 8 + it;                                              \
            const float* src = (j < 32)                                         \
                ? (g_tab + (size_t)j * NS + s0 + pc * 4)                        \
                : (hb + (size_t)(j - 32) * NS + s0 + pc * 4);                   \
            CPA16(s2u(&Bs[bf][it * 256 + pc * 4]), src);                        \
        }                                                                       \
        CPC();                                                                  \
    } while (0)

    unsigned long long acc[4][8];
#pragma unroll
    for (int ss = 0; ss < 4; ss++)
#pragma unroll
        for (int p = 0; p < 8; p++) acc[ss][p] = 0ull;

    INV_STAGE(0, 0);   // commits A + chunk0 as group 0
    for (int ch = 0; ch < 12; ch++) {
        if (ch < 11) { INV_STAGE(ch + 1, (ch + 1) & 1); CPW(1); }
        else CPW(0);
        __syncthreads();
        const float* Bc = Bs[ch & 1];
#pragma unroll
        for (int it = 0; it < 8; it++)
            GEMM_STEP_O(ch * 8 + it, Bc, it);
        __syncthreads();
    }
#undef INV_STAGE
    INV_EPILOGUE(g_h[nxt] + (size_t)(b * NW) * NS + s0);
}

// ================= layer-0 fused inverse: K = 32 basis + 2 x channels =================
__global__ void __launch_bounds__(256, 2) k_inv0(const float* __restrict__ x, int nxt) {
    __shared__ float Ad[34 * 64];
    __shared__ float Bs[2][16 * 256];
    int t = threadIdx.x;
    int og = t >> 6, sg = t & 63;
    int o0 = og * 16;
    int b = blockIdx.y;
    int s0 = blockIdx.x * 256;
    const float* cfb = g_coef + (size_t)b * NC * NW;

    // async A-prologue: 34 rows, contiguous copies (coef + g_cw0)
#pragma unroll
    for (int k2 = 0; k2 < 3; k2++) {
        int q = t + k2 * 256;
        if (q < 544) {
            int r = q >> 4, pc = q & 15;
            const float* src = (r < 32) ? (cfb + r * NW + pc * 4)
                                        : (g_cw0 + (r - 32) * NW + pc * 4);
            CPA16(s2u(&Ad[r * 64 + pc * 4]), src);
        }
    }

    unsigned long long acc[4][8];
#pragma unroll
    for (int ss = 0; ss < 4; ss++)
#pragma unroll
        for (int p = 0; p < 8; p++) acc[ss][p] = 0ull;

    // prefetch both tab chunks (chunk0 commits together with A as group 0)
#pragma unroll
    for (int ch = 0; ch < 2; ch++) {
#pragma unroll
        for (int k2 = 0; k2 < 4; k2++) {
            int q = t + k2 * 256;
            int it = q >> 6, pc = q & 63;
            int j = ch * 16 + it;
            CPA16(s2u(&Bs[ch][it * 256 + pc * 4]),
                  g_tab + (size_t)j * NS + s0 + pc * 4);
        }
        CPC();
    }
    for (int ch = 0; ch < 2; ch++) {
        if (ch == 0) CPW(1); else CPW(0);
        __syncthreads();
        const float* Bc = Bs[ch];
#pragma unroll 4
        for (int it = 0; it < 16; it++)
            GEMM_STEP_O(ch * 16 + it, Bc, it);
        __syncthreads();
    }
    // x-channel rows (interleaved source -> manual stage)
    {
        const float2* x2 = (const float2*)x + (size_t)b * NS + s0;
        float2 xv = x2[t];
        Bs[0][0 * 256 + t] = xv.x;
        Bs[0][1 * 256 + t] = xv.y;
    }
    __syncthreads();
#pragma unroll
    for (int it = 0; it < 2; it++)
        GEMM_STEP_O(32 + it, Bs[0], it);
    INV_EPILOGUE(g_h[nxt] + (size_t)(b * NW) * NS + s0);
}

// ================= head =================
__global__ void __launch_bounds__(256, 2) k_head(const float* __restrict__ qw,
                                                 const float* __restrict__ qb,
                                                 const float* __restrict__ ow,
                                                 const float* __restrict__ ob,
                                                 float* __restrict__ out, int cur) {
    __shared__ float Aq[64 * 36];
    __shared__ float Bq[2][16 * 260];
    int t = threadIdx.x;
    int qg = t >> 5, sg = t & 31;
    int b = blockIdx.y;
    int s0 = blockIdx.x * 256;
    for (int idx = t; idx < 64 * 32; idx += 256) {
        int i = idx >> 5, q = idx & 31;
        Aq[i * 36 + q] = qw[i * 32 + q];
    }
    unsigned long long acc[4][4];
#pragma unroll
    for (int qq = 0; qq < 4; qq++)
#pragma unroll
        for (int sp = 0; sp < 4; sp++) acc[qq][sp] = 0ull;

    const float* hb = g_h[cur] + (size_t)(b * NW) * NS;
#define HEAD_STAGE(ch, bf) do {                                                 \
        _Pragma("unroll")                                                       \
        for (int k2 = 0; k2 < 4; k2++) {                                        \
            int q = t + k2 * 256;                                               \
            int it = q >> 6, pc = q & 63;                                       \
            CPA16(s2u(&Bq[bf][it * 260 + pc * 4]),                              \
                  hb + (size_t)((ch) * 16 + it) * NS + s0 + pc * 4);            \
        }                                                                       \
        CPC();                                                                  \
    } while (0)

    HEAD_STAGE(0, 0);
    for (int ch = 0; ch < 4; ch++) {
        if (ch < 3) { HEAD_STAGE(ch + 1, (ch + 1) & 1); CPW(1); }
        else CPW(0);
        __syncthreads();
        const float* Bc = Bq[ch & 1];
#pragma unroll 4
        for (int it = 0; it < 16; it++) {
            int i = ch * 16 + it;
            float4 a0 = *(const float4*)&Aq[i * 36 + qg * 4];
            ulonglong2 B0 = *(const ulonglong2*)&Bc[it * 260 + sg * 4];
            ulonglong2 B1 = *(const ulonglong2*)&Bc[it * 260 + 128 + sg * 4];
            unsigned long long ad;
            ad = pk2(a0.x);
            fma2(acc[0][0], ad, B0.x); fma2(acc[0][1], ad, B0.y);
            fma2(acc[0][2], ad, B1.x); fma2(acc[0][3], ad, B1.y);
            ad = pk2(a0.y);
            fma2(acc[1][0], ad, B0.x); fma2(acc[1][1], ad, B0.y);
            fma2(acc[1][2], ad, B1.x); fma2(acc[1][3], ad, B1.y);
            ad = pk2(a0.z);
            fma2(acc[2][0], ad, B0.x); fma2(acc[2][1], ad, B0.y);
            fma2(acc[2][2], ad, B1.x); fma2(acc[2][3], ad, B1.y);
            ad = pk2(a0.w);
            fma2(acc[3][0], ad, B0.x); fma2(acc[3][1], ad, B0.y);
            fma2(acc[3][2], ad, B1.x); fma2(acc[3][3], ad, B1.y);
        }
        __syncthreads();
    }
#undef HEAD_STAGE
    float* BQ = &Bq[0][0];   // reuse both halves as qa[32][260]
#pragma unroll
    for (int qq = 0; qq < 4; qq++) {
        int q = qg * 4 + qq;
        float qbv = qb[q];
#pragma unroll
        for (int sp = 0; sp < 4; sp++) {
            float2 v = up2(acc[qq][sp]);
            int sl = (sp >> 1) * 128 + sg * 4 + (sp & 1) * 2;
            BQ[q * 260 + sl] = ftanh(v.x + qbv);
            BQ[q * 260 + sl + 1] = ftanh(v.y + qbv);
        }
    }
    __syncthreads();
    float r = ob[0];
#pragma unroll 8
    for (int q = 0; q < 32; q++) r = fmaf(BQ[q * 260 + t], ow[q], r);
    out[(size_t)b * NS + s0 + t] = r;
}

// ================= launcher =================
extern "C" void kernel_launch(void* const* d_in, const int* in_sizes, int n_in,
                              void* d_out, int out_size) {
    const float* x  = (const float*)d_in[0];
    const float* pw = (const float*)d_in[1];
    const float* pb = (const float*)d_in[2];
    const float* wr = (const float*)d_in[3];
    const float* wi = (const float*)d_in[4];
    const float* cw = (const float*)d_in[5];
    const float* cb = (const float*)d_in[6];
    const float* qw = (const float*)d_in[7];
    const float* qb = (const float*)d_in[8];
    const float* ow = (const float*)d_in[9];
    const float* ob = (const float*)d_in[10];
    float* out = (float*)d_out;

    k_tab<<<37, 256>>>(cw, pw, pb);                        // 1
    k_xdft<<<NB, 256>>>(x);                                // 2
    k_mix2<<<dim3(NM, 16), 256>>>(wr, wi, cb, 0, pw, pb);  // 3
    k_inv0<<<dim3(NS / 256, NB), 256>>>(x, 0);             // 4  <- profiled slot
    int cur = 0;
    for (int l = 1; l < NL; l++) {
        k_fwd<<<dim3(NSPLIT, NB), 128>>>(cur);
        k_red<<<(NB * NW * NC) / 256, 256>>>();
        k_mix2<<<dim3(NM, 16), 256>>>(wr, wi, cb, l, pw, pb);
        k_inv<<<dim3(NS / 256, NB), 256>>>(l, cur, 1 - cur);
        cur ^= 1;
    }
    k_head<<<dim3(NS / 256, NB), 256>>>(qw, qb, ow, ob, out, cur);
}